// round 3
// baseline (speedup 1.0000x reference)
#include <cuda_runtime.h>
#include <math.h>
#include <stdint.h>

// Problem constants (fixed shapes from the reference setup)
#define BQ    4
#define NP    16384
#define SQ    2048
#define KNN   32
#define NQTOT (BQ*SQ)          // 8192 query points
#define MROWS (NQTOT*KNN)      // 262144 grouped rows
#define RAD2  0.04f
#define BN_EPS 1e-5f

typedef unsigned long long ULL;

// ---------------- scratch (device globals; no allocations allowed) ----------
__device__ int   g_idx[MROWS];
__device__ float g_h1[(size_t)MROWS*64];
__device__ float g_h2[(size_t)MROWS*64];
__device__ float g_h3[(size_t)MROWS*128];
__device__ float g_sum[3*128];
__device__ float g_sq[3*128];
__device__ float g_scale[3*128];
__device__ float g_shift[3*128];

// ---------------- packed f32x2 FMA (SASS FFMA2; bit-identical to 2x fmaf) ---
__device__ __forceinline__ void fma2(ULL &d, ULL a, ULL b) {
    asm("fma.rn.f32x2 %0, %1, %2, %0;" : "+l"(d) : "l"(a), "l"(b));
}
__device__ __forceinline__ float2 unpack2(ULL v) {
    float2 r;
    asm("mov.b64 {%0, %1}, %2;" : "=f"(r.x), "=f"(r.y) : "l"(v));
    return r;
}

// ---------------- stats reset (graph replays re-run this) -------------------
__global__ void zero_stats_kernel() {
    int t = threadIdx.x + blockIdx.x * blockDim.x;
    if (t < 3*128) { g_sum[t] = 0.f; g_sq[t] = 0.f; }
}

// ---------------- ball query: warp per query, early exit --------------------
// FROZEN: rounding pattern replicates the reference lowering exactly.
__global__ void ballquery_kernel(const float* __restrict__ xyz,
                                 const float* __restrict__ newxyz) {
    int warp = (blockIdx.x * blockDim.x + threadIdx.x) >> 5;
    int lane = threadIdx.x & 31;
    if (warp >= NQTOT) return;
    int b = warp / SQ;
    const float* q = newxyz + (size_t)warp * 3;
    float qx = q[0], qy = q[1], qz = q[2];
    float qq = __fadd_rn(__fadd_rn(__fmul_rn(qx,qx), __fmul_rn(qy,qy)),
                         __fmul_rn(qz,qz));
    const float* xb = xyz + (size_t)b * NP * 3;
    int* outp = g_idx + (size_t)warp * KNN;
    int cnt = 0;
    int first = -1;
    for (int base = 0; base < NP; base += 32) {
        int p = base + lane;
        float x = xb[p*3+0], y = xb[p*3+1], z = xb[p*3+2];
        float xx = __fadd_rn(__fadd_rn(__fmul_rn(x,x), __fmul_rn(y,y)),
                             __fmul_rn(z,z));
        float dt = fmaf(qz, z, fmaf(qy, y, __fmul_rn(qx, x)));
        float d2 = __fsub_rn(__fadd_rn(qq, xx), __fmul_rn(2.0f, dt));
        bool hit = !(d2 > RAD2);
        unsigned mask = __ballot_sync(0xffffffffu, hit);
        if (mask) {
            if (first < 0) first = base + __ffs(mask) - 1;
            int pos = cnt + __popc(mask & ((1u << lane) - 1u));
            if (hit && pos < KNN) outp[pos] = p;
            cnt += __popc(mask);
            if (cnt >= KNN) break;
        }
    }
    if (cnt < KNN) {
        if (first < 0) first = 0;
        for (int pos = cnt + lane; pos < KNN; pos += 32) outp[pos] = first;
    }
}

// ---------------- f32x2 GEMM core: 256 rows x 64 cols per block -------------
// Xs: [CIN][256] floats. Wd: [CIN][64] float2 pre-duplicated (w,w) pairs.
// Warp w owns cols 8w..8w+7 (broadcast W loads). Thread lane owns rows
// {4*lane .. 4*lane+3} and {128+4*lane .. +3}: X pairs via conflict-free LDS.128.
template<int CIN>
__device__ __forceinline__ void gemm_core(const float* Xs, const float2* Wd,
                                          ULL acc[4][8], int lane, int cb)
{
    #pragma unroll 8
    for (int c = 0; c < CIN; c++) {
        ulonglong2 xa = *reinterpret_cast<const ulonglong2*>(Xs + c*256 + 4*lane);
        ulonglong2 xb = *reinterpret_cast<const ulonglong2*>(Xs + c*256 + 128 + 4*lane);
        const ulonglong2* wp = reinterpret_cast<const ulonglong2*>(Wd + c*64 + cb);
        ulonglong2 w0 = wp[0], w1 = wp[1], w2 = wp[2], w3 = wp[3];
        fma2(acc[0][0], xa.x, w0.x); fma2(acc[0][1], xa.x, w0.y);
        fma2(acc[0][2], xa.x, w1.x); fma2(acc[0][3], xa.x, w1.y);
        fma2(acc[0][4], xa.x, w2.x); fma2(acc[0][5], xa.x, w2.y);
        fma2(acc[0][6], xa.x, w3.x); fma2(acc[0][7], xa.x, w3.y);
        fma2(acc[1][0], xa.y, w0.x); fma2(acc[1][1], xa.y, w0.y);
        fma2(acc[1][2], xa.y, w1.x); fma2(acc[1][3], xa.y, w1.y);
        fma2(acc[1][4], xa.y, w2.x); fma2(acc[1][5], xa.y, w2.y);
        fma2(acc[1][6], xa.y, w3.x); fma2(acc[1][7], xa.y, w3.y);
        fma2(acc[2][0], xb.x, w0.x); fma2(acc[2][1], xb.x, w0.y);
        fma2(acc[2][2], xb.x, w1.x); fma2(acc[2][3], xb.x, w1.y);
        fma2(acc[2][4], xb.x, w2.x); fma2(acc[2][5], xb.x, w2.y);
        fma2(acc[2][6], xb.x, w3.x); fma2(acc[2][7], xb.x, w3.y);
        fma2(acc[3][0], xb.y, w0.x); fma2(acc[3][1], xb.y, w0.y);
        fma2(acc[3][2], xb.y, w1.x); fma2(acc[3][3], xb.y, w1.y);
        fma2(acc[3][4], xb.y, w2.x); fma2(acc[3][5], xb.y, w2.y);
        fma2(acc[3][6], xb.y, w3.x); fma2(acc[3][7], xb.y, w3.y);
    }
}

// Epilogue: bias add, store Y, per-channel sum/sumsq to smem then global.
__device__ __forceinline__ void gemm_epilogue(
    ULL acc[4][8], int m0, int lane, int cb, int t, int nOff, int COUTfull,
    const float* __restrict__ bias, float* __restrict__ Y,
    float* s_sum, float* s_sq,
    float* __restrict__ gsum, float* __restrict__ gsq)
{
    float colSum[8], colSq[8], bv[8];
    #pragma unroll
    for (int j = 0; j < 8; j++) { colSum[j] = 0.f; colSq[j] = 0.f; bv[j] = bias[cb + j]; }
    #pragma unroll
    for (int p = 0; p < 4; p++) {
        int rbase = ((p >> 1) ? 128 : 0) + 4*lane + 2*(p & 1);
        float vlo[8], vhi[8];
        #pragma unroll
        for (int j = 0; j < 8; j++) {
            float2 v = unpack2(acc[p][j]);
            float a = v.x + bv[j], b = v.y + bv[j];
            vlo[j] = a; vhi[j] = b;
            colSum[j] += a + b;
            colSq[j] = fmaf(a, a, colSq[j]);
            colSq[j] = fmaf(b, b, colSq[j]);
        }
        float* d0 = Y + (size_t)(m0 + rbase) * COUTfull + nOff + cb;
        float* d1 = d0 + COUTfull;
        *reinterpret_cast<float4*>(d0)     = make_float4(vlo[0], vlo[1], vlo[2], vlo[3]);
        *reinterpret_cast<float4*>(d0 + 4) = make_float4(vlo[4], vlo[5], vlo[6], vlo[7]);
        *reinterpret_cast<float4*>(d1)     = make_float4(vhi[0], vhi[1], vhi[2], vhi[3]);
        *reinterpret_cast<float4*>(d1 + 4) = make_float4(vhi[4], vhi[5], vhi[6], vhi[7]);
    }
    #pragma unroll
    for (int j = 0; j < 8; j++) {
        atomicAdd(&s_sum[cb + j], colSum[j]);
        atomicAdd(&s_sq[cb + j],  colSq[j]);
    }
    __syncthreads();
    if (t < 64) {
        atomicAdd(&gsum[nOff + t], s_sum[t]);
        atomicAdd(&gsq[nOff + t],  s_sq[t]);
    }
}

// ---------------- layer 1: gather (ballquery idx) + GEMM 67->64 -------------
__global__ void __launch_bounds__(256, 2)
gemm1_kernel(const float* __restrict__ xyz,
             const float* __restrict__ points,
             const float* __restrict__ newxyz,
             const float* __restrict__ W,     // [64][67]
             const float* __restrict__ bias,
             float* __restrict__ Y,
             float* __restrict__ gsum,
             float* __restrict__ gsq)
{
    constexpr int CIN = 67;
    extern __shared__ float sm[];
    float*  Xs    = sm;                                   // [67][256]
    float2* Wd    = reinterpret_cast<float2*>(sm + CIN*256);  // [67][64] dup
    float*  s_sum = reinterpret_cast<float*>(Wd + CIN*64);
    float*  s_sq  = s_sum + 64;
    const int t    = threadIdx.x;
    const int lane = t & 31;
    const int warp = t >> 5;
    const int cb   = warp * 8;
    const int m0   = blockIdx.x * 256;

    for (int i = t; i < 64*CIN; i += 256) {
        int o = i / CIN, c = i - o*CIN;
        float w = W[i];
        Wd[c*64 + o] = make_float2(w, w);
    }
    if (t < 64) { s_sum[t] = 0.f; s_sq[t] = 0.f; }

    {   // gather: one thread per row
        const int r = t;
        const int m = m0 + r;
        const int b = m >> 16;                 // / (SQ*KNN)
        const int s = (m >> 5) & (SQ - 1);
        const int j = g_idx[m];
        const float4* prow =
            reinterpret_cast<const float4*>(points + (size_t)(b*NP + j) * 64);
        #pragma unroll
        for (int v = 0; v < 16; v++) {
            float4 x = prow[v];
            int c = 3 + v*4;
            Xs[(c+0)*256 + r] = x.x;
            Xs[(c+1)*256 + r] = x.y;
            Xs[(c+2)*256 + r] = x.z;
            Xs[(c+3)*256 + r] = x.w;
        }
        const float* pj = xyz    + (size_t)(b*NP + j) * 3;
        const float* qv = newxyz + (size_t)(b*SQ + s) * 3;
        Xs[0*256 + r] = pj[0] - qv[0];
        Xs[1*256 + r] = pj[1] - qv[1];
        Xs[2*256 + r] = pj[2] - qv[2];
    }
    __syncthreads();

    ULL acc[4][8];
    #pragma unroll
    for (int p = 0; p < 4; p++)
        #pragma unroll
        for (int j = 0; j < 8; j++) acc[p][j] = 0ull;

    gemm_core<CIN>(Xs, Wd, acc, lane, cb);
    gemm_epilogue(acc, m0, lane, cb, t, 0, 64, bias, Y, s_sum, s_sq, gsum, gsq);
}

// ---------------- layers 2/3: BN+ReLU(prev) folded into load, then GEMM -----
// Grid.y tiles the output channels in 64-wide slabs (layer3: gridDim.y = 2).
__global__ void __launch_bounds__(256, 2)
gemm_bn_kernel(const float* __restrict__ Xpre,
               const float* __restrict__ W,     // [COUTtot][64]
               const float* __restrict__ bias,
               const float* __restrict__ scl,
               const float* __restrict__ shf,
               float* __restrict__ Y,
               int COUTfull,
               float* __restrict__ gsum,
               float* __restrict__ gsq)
{
    constexpr int CIN = 64;
    extern __shared__ float sm[];
    float*  Xs    = sm;                                   // [64][256]
    float2* Wd    = reinterpret_cast<float2*>(sm + CIN*256);  // [64][64] dup
    float*  s_sum = reinterpret_cast<float*>(Wd + CIN*64);
    float*  s_sq  = s_sum + 64;
    const int t    = threadIdx.x;
    const int lane = t & 31;
    const int warp = t >> 5;
    const int cb   = warp * 8;
    const int m0   = blockIdx.x * 256;
    const int nOff = blockIdx.y * 64;

    const float* Wblk = W + (size_t)nOff * CIN;
    for (int i = t; i < 64*CIN; i += 256) {
        int o = i >> 6, c = i & 63;
        float w = Wblk[i];
        Wd[c*64 + o] = make_float2(w, w);
    }
    if (t < 64) { s_sum[t] = 0.f; s_sq[t] = 0.f; }

    {   // BN + ReLU fold while staging previous activations
        const int r = t;
        const float4* src =
            reinterpret_cast<const float4*>(Xpre + (size_t)(m0 + r) * CIN);
        #pragma unroll
        for (int v = 0; v < 16; v++) {
            float4 x = src[v];
            int c = v*4;
            Xs[(c+0)*256 + r] = fmaxf(fmaf(x.x, scl[c+0], shf[c+0]), 0.f);
            Xs[(c+1)*256 + r] = fmaxf(fmaf(x.y, scl[c+1], shf[c+1]), 0.f);
            Xs[(c+2)*256 + r] = fmaxf(fmaf(x.z, scl[c+2], shf[c+2]), 0.f);
            Xs[(c+3)*256 + r] = fmaxf(fmaf(x.w, scl[c+3], shf[c+3]), 0.f);
        }
    }
    __syncthreads();

    ULL acc[4][8];
    #pragma unroll
    for (int p = 0; p < 4; p++)
        #pragma unroll
        for (int j = 0; j < 8; j++) acc[p][j] = 0ull;

    gemm_core<CIN>(Xs, Wd, acc, lane, cb);
    gemm_epilogue(acc, m0, lane, cb, t, nOff, COUTfull,
                  bias + nOff, Y, s_sum, s_sq, gsum, gsq);
}

// ---------------- BN finalize: scale/shift per channel ----------------------
__global__ void finalize_kernel(const float* __restrict__ gamma,
                                const float* __restrict__ beta,
                                int layer, int cout)
{
    int c = threadIdx.x;
    if (c < cout) {
        const float invM = 1.0f / (float)MROWS;
        float mean = g_sum[layer*128 + c] * invM;
        float var  = g_sq[layer*128 + c] * invM - mean*mean;
        float rs = rsqrtf(var + BN_EPS);
        float sc = gamma[c] * rs;
        g_scale[layer*128 + c] = sc;
        g_shift[layer*128 + c] = beta[c] - mean*sc;
    }
}

// ---------------- BN3 + ReLU + max over K + transpose -----------------------
__global__ void maxpool_kernel(float* __restrict__ out)
{
    const int q = blockIdx.x;      // b*SQ + s
    const int o = threadIdx.x;     // channel 0..127
    const int b = q / SQ, s = q - b*SQ;
    const float sc = g_scale[2*128 + o];
    const float sh = g_shift[2*128 + o];
    const float* h = g_h3 + (size_t)q * KNN * 128 + o;
    float mx = -3.402823466e38f;
    #pragma unroll
    for (int k = 0; k < KNN; k++)
        mx = fmaxf(mx, fmaf(h[(size_t)k*128], sc, sh));
    out[(size_t)(b*128 + o) * SQ + s] = fmaxf(mx, 0.f);
}

// ---------------- launch ------------------------------------------------
extern "C" void kernel_launch(void* const* d_in, const int* in_sizes, int n_in,
                              void* d_out, int out_size) {
    const float* xyz    = (const float*)d_in[0];
    const float* points = (const float*)d_in[1];
    const float* newxyz = (const float*)d_in[2];
    const float* W1 = (const float*)d_in[3],  *b1 = (const float*)d_in[4];
    const float* ga1 = (const float*)d_in[5], *be1 = (const float*)d_in[6];
    const float* W2 = (const float*)d_in[7],  *b2 = (const float*)d_in[8];
    const float* ga2 = (const float*)d_in[9], *be2 = (const float*)d_in[10];
    const float* W3 = (const float*)d_in[11], *b3 = (const float*)d_in[12];
    const float* ga3 = (const float*)d_in[13], *be3 = (const float*)d_in[14];

    float* out = (float*)d_out;
    float* outPts = out;
    if (out_size == BQ*SQ*3 + BQ*128*SQ) {
        cudaMemcpyAsync(out, newxyz, sizeof(float)*BQ*SQ*3, cudaMemcpyDeviceToDevice);
        outPts = out + BQ*SQ*3;
    }

    float *h1, *h2, *h3, *gsum, *gsq, *gscale, *gshift;
    cudaGetSymbolAddress((void**)&h1, g_h1);
    cudaGetSymbolAddress((void**)&h2, g_h2);
    cudaGetSymbolAddress((void**)&h3, g_h3);
    cudaGetSymbolAddress((void**)&gsum, g_sum);
    cudaGetSymbolAddress((void**)&gsq, g_sq);
    cudaGetSymbolAddress((void**)&gscale, g_scale);
    cudaGetSymbolAddress((void**)&gshift, g_shift);

    const int smem1 = 67*256*4 + 67*64*8 + 2*64*4;    // 103,424 B
    const int smem2 = 64*256*4 + 64*64*8 + 2*64*4;    //  98,816 B
    cudaFuncSetAttribute(gemm1_kernel, cudaFuncAttributeMaxDynamicSharedMemorySize, smem1);
    cudaFuncSetAttribute(gemm_bn_kernel, cudaFuncAttributeMaxDynamicSharedMemorySize, smem2);

    zero_stats_kernel<<<1, 512>>>();
    ballquery_kernel<<<NQTOT/8, 256>>>(xyz, newxyz);

    gemm1_kernel<<<MROWS/256, 256, smem1>>>(xyz, points, newxyz, W1, b1,
                                            h1, gsum + 0, gsq + 0);
    finalize_kernel<<<1, 128>>>(ga1, be1, 0, 64);

    gemm_bn_kernel<<<dim3(MROWS/256, 1), 256, smem2>>>(h1, W2, b2,
                                                       gscale + 0, gshift + 0,
                                                       h2, 64, gsum + 128, gsq + 128);
    finalize_kernel<<<1, 128>>>(ga2, be2, 1, 64);

    gemm_bn_kernel<<<dim3(MROWS/256, 2), 256, smem2>>>(h2, W3, b3,
                                                       gscale + 128, gshift + 128,
                                                       h3, 128, gsum + 256, gsq + 256);
    finalize_kernel<<<1, 128>>>(ga3, be3, 2, 128);

    maxpool_kernel<<<NQTOT, 128>>>(outPts);
}